// round 17
// baseline (speedup 1.0000x reference)
#include <cuda_runtime.h>

typedef unsigned long long ull;

#define T_STEPS 1024
#define BATCH   64
#define NCTA    128
#define NTHR    768

// R15 skeleton (best: 14.2ms — full unroll + immediate offsets + tree barrier +
// 2-wave reduction; xg0 hoist retired) with ONE change: lane retile to cut L1
// wavefronts ~27%.
//   OLD lane tile: pg(16 pair-groups) x cl(2 col-halves): per c8 row 1 LDG(2wf)+4 LDS(4wf)
//   NEW lane tile: q(8 quad-groups) x c2(4 col-quarters = gate index):
//     per c8 row: 2 LDG.128 (128B contiguous each = 1wf) + 2 LDS.128 (64B = 1wf) -> 4wf
//     per c4 row: 2 LDG + 1 LDS -> 3wf
//   Lane (q,c2) covers L0 cols c2*4..c2*4+3, L1 cols c2*2,c2*2+1,
//   pairs {2q, 2q+1, 2q+16, 2q+17} (batches 4q..4q+3 and 32+4q..32+4q+3).
//
// v (K=1024 rows x 64 batch) read directly from global (L2):
//   rows [0,256) = x_t; [256,768) = h0_{t-1}; [768,1024) = h1_{t-2}
// Warp ks (0..23) owns k in [32ks,32ks+32) for BOTH layers (contiguous, no dup reads).
// Accums: a0[16] + a1[8] = 24 ull. 2-wave 12-slot reduction (2 syncs).

__device__ float g_xT[T_STEPS * 256 * BATCH];   // x transposed to [t][k][b]
__device__ float g_h0[2][512 * BATCH];
__device__ float g_h1[2][256 * BATCH];
__device__ unsigned g_leaf[8 * 128];            // leaf counters, 512B stride
__device__ unsigned g_root = 0;
__device__ unsigned g_rel  = 0;
__device__ unsigned g_done = 0;

__device__ __forceinline__ ull ffma2(ull a, ull b, ull c) {
    ull d;
    asm("fma.rn.f32x2 %0, %1, %2, %3;" : "=l"(d) : "l"(a), "l"(b), "l"(c));
    return d;
}
__device__ __forceinline__ ull addf2(ull a, ull b) {
    ull d;
    asm("add.rn.f32x2 %0, %1, %2;" : "=l"(d) : "l"(a), "l"(b));
    return d;
}
__device__ __forceinline__ ull dup32(float w) {
    unsigned u = __float_as_uint(w);
    return ((ull)u << 32) | (ull)u;
}
__device__ __forceinline__ float sigmf(float x) {
    return 1.0f / (1.0f + __expf(-x));
}

// Tree grid barrier, sequence number s (monotone per launch).
// Safe: ~222KB smem -> 1 CTA/SM, 128 CTAs <= 148 SMs, all co-resident in wave 1.
__device__ __forceinline__ void grid_barrier(int& s) {
    __syncthreads();
    if (threadIdx.x == 0) {
        s += 1;
        __threadfence();
        unsigned old = atomicAdd(&g_leaf[(blockIdx.x >> 4) * 128], 1u);
        if (old + 1u == 16u * (unsigned)s) {              // last in leaf -> promote
            unsigned old2 = atomicAdd(&g_root, 1u);
            if (old2 + 1u == 8u * (unsigned)s) {          // last leaf -> release
                __threadfence();
                atomicAdd(&g_rel, 1u);
            }
        }
        while (*(volatile unsigned*)&g_rel < (unsigned)s) __nanosleep(32);
        __threadfence();
    }
    __syncthreads();
}

// 32-row L0 slice: 4 cols (gate c2) x 4 pairs. FULLY UNROLLED, immediate offsets.
// vrow: ulonglong2 row base (NOT lane-offset); wrow: ull row base.
__device__ __forceinline__ void gemm32_c8q(const ulonglong2* __restrict__ vrow,
                                           const ull* __restrict__ wrow,
                                           ull* __restrict__ a, int q, int c2) {
#pragma unroll
    for (int r = 0; r < 32; r++) {
        ulonglong2 vA = vrow[r * 16 + q];          // pairs 2q, 2q+1
        ulonglong2 vB = vrow[r * 16 + q + 8];      // pairs 2q+16, 2q+17
        const ulonglong2* w2 =
            reinterpret_cast<const ulonglong2*>(wrow + r * 16) + c2 * 2;
        ulonglong2 wA = w2[0];                     // cols c2*4, c2*4+1
        ulonglong2 wB = w2[1];                     // cols c2*4+2, c2*4+3
        a[0]  = ffma2(wA.x, vA.x, a[0]);   a[1]  = ffma2(wA.x, vA.y, a[1]);
        a[2]  = ffma2(wA.x, vB.x, a[2]);   a[3]  = ffma2(wA.x, vB.y, a[3]);
        a[4]  = ffma2(wA.y, vA.x, a[4]);   a[5]  = ffma2(wA.y, vA.y, a[5]);
        a[6]  = ffma2(wA.y, vB.x, a[6]);   a[7]  = ffma2(wA.y, vB.y, a[7]);
        a[8]  = ffma2(wB.x, vA.x, a[8]);   a[9]  = ffma2(wB.x, vA.y, a[9]);
        a[10] = ffma2(wB.x, vB.x, a[10]);  a[11] = ffma2(wB.x, vB.y, a[11]);
        a[12] = ffma2(wB.y, vA.x, a[12]);  a[13] = ffma2(wB.y, vA.y, a[13]);
        a[14] = ffma2(wB.y, vB.x, a[14]);  a[15] = ffma2(wB.y, vB.y, a[15]);
    }
}

// 32-row L1 slice: 2 cols (gate c2) x 4 pairs. FULLY UNROLLED, immediate offsets.
__device__ __forceinline__ void gemm32_c4q(const ulonglong2* __restrict__ vrow,
                                           const ull* __restrict__ wrow,
                                           ull* __restrict__ a, int q, int c2) {
#pragma unroll
    for (int r = 0; r < 32; r++) {
        ulonglong2 vA = vrow[r * 16 + q];
        ulonglong2 vB = vrow[r * 16 + q + 8];
        ulonglong2 wA =
            reinterpret_cast<const ulonglong2*>(wrow + r * 8)[c2];  // cols c2*2, c2*2+1
        a[0] = ffma2(wA.x, vA.x, a[0]);  a[1] = ffma2(wA.x, vA.y, a[1]);
        a[2] = ffma2(wA.x, vB.x, a[2]);  a[3] = ffma2(wA.x, vB.y, a[3]);
        a[4] = ffma2(wA.y, vA.x, a[4]);  a[5] = ffma2(wA.y, vA.y, a[5]);
        a[6] = ffma2(wA.y, vB.x, a[6]);  a[7] = ffma2(wA.y, vB.y, a[7]);
    }
}

__global__ void __launch_bounds__(NTHR, 1)
lstm2_kernel(const float* __restrict__ x,
             const float* __restrict__ Wih0, const float* __restrict__ bih0,
             const float* __restrict__ Whh0, const float* __restrict__ bhh0,
             const float* __restrict__ Wih1, const float* __restrict__ bih1,
             const float* __restrict__ Whh1, const float* __restrict__ bhh1,
             float* __restrict__ out)
{
    extern __shared__ char smraw[];
    ull*   w0d    = reinterpret_cast<ull*>(smraw);            // [768][16] lane-dup
    ull*   w1d    = w0d + 768 * 16;                           // [768][8]
    float* bcol   = reinterpret_cast<float*>(w1d + 768 * 8);  // [24] pad 32
    float* gates0 = bcol + 32;                                // [16][64]
    float* gates1 = gates0 + 16 * BATCH;                      // [8][64]
    ull*   red0   = reinterpret_cast<ull*>(gates1 + 8 * BATCH); // [16][12][32]
    ull*   red1   = red0 + 16 * 12 * 32;                      // [8][12][32]

    const int tid = threadIdx.x;
    const int cta = blockIdx.x;
    const int ks  = tid >> 5;            // warp id 0..23: k in [32ks, 32ks+32)
    const int q   = (tid & 31) >> 2;     // quad group 0..7
    const int c2  = tid & 3;             // col quarter = gate index
    int bar_s = 0;                       // barrier sequence (thread 0 uses)

    // ---- one-time: transpose x (B,T,K) -> g_xT (T,K,B) ----
    {
        const size_t total = (size_t)BATCH * T_STEPS * 64;    // float4 groups
        for (size_t idx = (size_t)cta * NTHR + tid; idx < total; idx += (size_t)NCTA * NTHR) {
            int b  = (int)(idx & 63);
            size_t r = idx >> 6;
            int kg = (int)(r & 63);
            int t  = (int)(r >> 6);
            float4 v4 = *reinterpret_cast<const float4*>(
                x + ((size_t)b * T_STEPS + t) * 256 + kg * 4);
            float* dst = g_xT + ((size_t)t * 256 + kg * 4) * BATCH + b;
            dst[0 * BATCH] = v4.x;
            dst[1 * BATCH] = v4.y;
            dst[2 * BATCH] = v4.z;
            dst[3 * BATCH] = v4.w;
        }
    }

    // ---- one-time: stage weights into smem (lane-duplicated for f32x2) ----
    // L0 smem col cc = g*4 + u -> global j = g*512 + cta*4 + u
    for (int idx = tid; idx < 768 * 16; idx += NTHR) {
        int k = idx >> 4, cc = idx & 15;
        int g = cc >> 2, u = cc & 3;
        int j = g * 512 + cta * 4 + u;
        float w = (k < 256) ? Wih0[(size_t)k * 2048 + j]
                            : Whh0[(size_t)(k - 256) * 2048 + j];
        w0d[idx] = dup32(w);
    }
    // L1 smem col cc = g*2 + u1 -> global j = g*256 + cta*2 + u1
    for (int idx = tid; idx < 768 * 8; idx += NTHR) {
        int k = idx >> 3, cc = idx & 7;
        int g = cc >> 1, u1 = cc & 1;
        int j = g * 256 + cta * 2 + u1;
        float w = (k < 512) ? Wih1[(size_t)k * 1024 + j]
                            : Whh1[(size_t)(k - 512) * 1024 + j];
        w1d[idx] = dup32(w);
    }
    if (tid < 16) {
        int g = tid >> 2, u = tid & 3;
        int j = g * 512 + cta * 4 + u;
        bcol[tid] = bih0[j] + bhh0[j];
    } else if (tid < 24) {
        int cc = tid - 16, g = cc >> 1, u1 = cc & 1;
        int j = g * 256 + cta * 2 + u1;
        bcol[tid] = bih1[j] + bhh1[j];
    }

    float cst = 0.0f;   // c0 for tid<256 (unit tid>>6, batch tid&63); c1 for [256,384)

    grid_barrier(bar_s);     // g_xT complete

    // ---- main recurrence: iteration t = layer0 step t + layer1 step t-1 ----
    for (int t = 0; t <= T_STEPS; t++) {
        const bool hasL0 = (t < T_STEPS);
        const bool hasL1 = (t >= 1);

        ull a0[16], a1[8];
#pragma unroll
        for (int j = 0; j < 16; j++) a0[j] = 0ull;
#pragma unroll
        for (int j = 0; j < 8; j++) a1[j] = 0ull;

        // ---- L0 slice: k in [32ks, 32ks+32); sources: ks<8 -> x_t, else h0_{t-1} ----
        if (hasL0 && (ks < 8 || t >= 1)) {
            const float* src = (ks < 8)
                ? (g_xT + (size_t)t * 16384 + ks * 2048)
                : (g_h0[(t - 1) & 1] + (ks - 8) * 2048);
            gemm32_c8q(reinterpret_cast<const ulonglong2*>(src),
                       w0d + (size_t)(32 * ks) * 16, a0, q, c2);
        }
        // ---- L1 slice: local k1 in [32ks, 32ks+32); ks<16 -> h0_{t-1}, else h1_{t-2} ----
        if (hasL1 && (ks < 16 || t >= 2)) {
            const float* src = (ks < 16)
                ? (g_h0[(t - 1) & 1] + ks * 2048)
                : (g_h1[t & 1] + (ks - 16) * 2048);
            gemm32_c4q(reinterpret_cast<const ulonglong2*>(src),
                       w1d + (size_t)(32 * ks) * 8, a1, q, c2);
        }

        // ---- 2-wave ks reduction into 12 slots ----
        const int slot = (ks < 12) ? ks : (ks - 12);
        if (ks < 12) {
#pragma unroll
            for (int j = 0; j < 4; j++) {
                ull* base = red0 + ((c2 * 4 + j) * 12 + slot) * 32;
                *reinterpret_cast<ulonglong2*>(base + 2 * q) =
                    make_ulonglong2(a0[j * 4 + 0], a0[j * 4 + 1]);
                *reinterpret_cast<ulonglong2*>(base + 2 * q + 16) =
                    make_ulonglong2(a0[j * 4 + 2], a0[j * 4 + 3]);
            }
#pragma unroll
            for (int j = 0; j < 2; j++) {
                ull* base = red1 + ((c2 * 2 + j) * 12 + slot) * 32;
                *reinterpret_cast<ulonglong2*>(base + 2 * q) =
                    make_ulonglong2(a1[j * 4 + 0], a1[j * 4 + 1]);
                *reinterpret_cast<ulonglong2*>(base + 2 * q + 16) =
                    make_ulonglong2(a1[j * 4 + 2], a1[j * 4 + 3]);
            }
        }
        __syncthreads();
        if (ks >= 12) {
#pragma unroll
            for (int j = 0; j < 4; j++) {
                ull* base = red0 + ((c2 * 4 + j) * 12 + slot) * 32;
                ulonglong2 rA = *reinterpret_cast<ulonglong2*>(base + 2 * q);
                ulonglong2 rB = *reinterpret_cast<ulonglong2*>(base + 2 * q + 16);
                rA.x = addf2(rA.x, a0[j * 4 + 0]); rA.y = addf2(rA.y, a0[j * 4 + 1]);
                rB.x = addf2(rB.x, a0[j * 4 + 2]); rB.y = addf2(rB.y, a0[j * 4 + 3]);
                *reinterpret_cast<ulonglong2*>(base + 2 * q)      = rA;
                *reinterpret_cast<ulonglong2*>(base + 2 * q + 16) = rB;
            }
#pragma unroll
            for (int j = 0; j < 2; j++) {
                ull* base = red1 + ((c2 * 2 + j) * 12 + slot) * 32;
                ulonglong2 rA = *reinterpret_cast<ulonglong2*>(base + 2 * q);
                ulonglong2 rB = *reinterpret_cast<ulonglong2*>(base + 2 * q + 16);
                rA.x = addf2(rA.x, a1[j * 4 + 0]); rA.y = addf2(rA.y, a1[j * 4 + 1]);
                rB.x = addf2(rB.x, a1[j * 4 + 2]); rB.y = addf2(rB.y, a1[j * 4 + 3]);
                *reinterpret_cast<ulonglong2*>(base + 2 * q)      = rA;
                *reinterpret_cast<ulonglong2*>(base + 2 * q + 16) = rB;
            }
        }
        __syncthreads();

        // ---- final: sum 12 slots + bias -> gates (one ull per thread) ----
        if (tid < 512) {
            int cc = tid >> 5, pr = tid & 31;
            const ull* r = red0 + (cc * 12) * 32 + pr;
            ull s = dup32(bcol[cc]);
#pragma unroll
            for (int w = 0; w < 12; w++) s = addf2(s, r[w * 32]);
            *reinterpret_cast<ull*>(&gates0[cc * 64 + 2 * pr]) = s;
        } else {
            int i = tid - 512, cc = i >> 5, pr = i & 31;
            const ull* r = red1 + (cc * 12) * 32 + pr;
            ull s = dup32(bcol[16 + cc]);
#pragma unroll
            for (int w = 0; w < 12; w++) s = addf2(s, r[w * 32]);
            *reinterpret_cast<ull*>(&gates1[cc * 64 + 2 * pr]) = s;
        }
        __syncthreads();

        // ---- activations (disjoint warps) ----
        if (hasL0 && tid < 256) {
            int u = tid >> 6, b = tid & 63;
            float gi = gates0[(0 * 4 + u) * 64 + b];
            float gf = gates0[(1 * 4 + u) * 64 + b];
            float gg = gates0[(2 * 4 + u) * 64 + b];
            float go = gates0[(3 * 4 + u) * 64 + b];
            cst = sigmf(gf) * cst + sigmf(gi) * tanhf(gg);
            g_h0[t & 1][(cta * 4 + u) * 64 + b] = sigmf(go) * tanhf(cst);
        }
        if (hasL1 && tid >= 256 && tid < 384) {
            int u1 = (tid >> 6) & 1, b = tid & 63;
            float gi = gates1[(0 * 2 + u1) * 64 + b];
            float gf = gates1[(1 * 2 + u1) * 64 + b];
            float gg = gates1[(2 * 2 + u1) * 64 + b];
            float go = gates1[(3 * 2 + u1) * 64 + b];
            cst = sigmf(gf) * cst + sigmf(gi) * tanhf(gg);
            float h = sigmf(go) * tanhf(cst);
            int s = t - 1;
            g_h1[s & 1][(cta * 2 + u1) * 64 + b] = h;
            out[((size_t)b * T_STEPS + s) * 256 + cta * 2 + u1] = h;
        }

        if (t < T_STEPS) grid_barrier(bar_s);
    }

    // ---- last CTA out resets all barrier counters (graph-replay safe) ----
    if (threadIdx.x == 0) {
        __threadfence();
        unsigned old = atomicAdd(&g_done, 1u);
        if (old == (unsigned)(NCTA - 1)) {
#pragma unroll
            for (int i = 0; i < 8; i++) g_leaf[i * 128] = 0u;
            g_root = 0u;
            g_rel  = 0u;
            __threadfence();
            g_done = 0u;
        }
    }
}

// smem: w0d 98304 + w1d 49152 + bcol 128 + gates 6144 + red0 49152 + red1 24576 = 227456
#define SMEM_BYTES (98304 + 49152 + 128 + 4096 + 2048 + 49152 + 24576)

extern "C" void kernel_launch(void* const* d_in, const int* in_sizes, int n_in,
                              void* d_out, int out_size) {
    (void)in_sizes; (void)n_in; (void)out_size;
    cudaFuncSetAttribute(lstm2_kernel,
                         cudaFuncAttributeMaxDynamicSharedMemorySize, SMEM_BYTES);
    lstm2_kernel<<<NCTA, NTHR, SMEM_BYTES>>>(
        (const float*)d_in[0],
        (const float*)d_in[1], (const float*)d_in[2],
        (const float*)d_in[3], (const float*)d_in[4],
        (const float*)d_in[5], (const float*)d_in[6],
        (const float*)d_in[7], (const float*)d_in[8],
        (float*)d_out);
}